// round 13
// baseline (speedup 1.0000x reference)
#include <cuda_runtime.h>
#include <cstdint>

// ColorCurveLearningLoss: cp.async.bulk staged pipeline + per-thread
// transposed smem histogram. 3 CTAs/SM, 24 warps, 108KB/SM in flight.
// mean_p - mean_t = sum(p-t)/cnt per (channel,bin) -> one packed 32-bit token
// per element: tok = 0x804000 + round(d*2^14)  (count bits [23,32), value [0,23))
// Overflow: <=29 stages * 4 = 116 elem/thread; value <= 116*2^15 = 3.8M < 2^23;
// count <= 116 < 512.
// Pipeline: 3-stage ring, each stage 3x4KB (x,p,t), tid0 issues cp.async.bulk
// with mbarrier complete_tx; consumers LDS.128 at tid*16 (conflict-free).
// Empty barrier counts per-WARP arrivals (8), lane0 only -> 32x less mbar traffic.
// Grid: 9 x 48 chunks = 432 blocks @ 3 CTA/SM = one wave.
// Globals self-clean via atomicExch in last block.

#define NBINS 32
#define NSEG 96
#define BLOCK 256
#define NWARP (BLOCK / 32)
#define BLK_PER_CHUNK 9
#define NSTAGE 3
#define SGROUPS 256                      // float4 groups per stage (= BLOCK)
#define STAGE_BYTES (SGROUPS * 16)       // 4096 per stream
#define MASK23 ((1u << 23) - 1u)

// dynamic smem layout
#define HIST_BYTES (NBINS * BLOCK * 4)           // 32768
#define RING_OFF   HIST_BYTES
#define RING_BYTES (NSTAGE * 3 * STAGE_BYTES)    // 36864
#define BAR_OFF    (RING_OFF + RING_BYTES)
#define SMEM_TOTAL (BAR_OFF + NSTAGE * 16)       // full/empty pairs

__device__ unsigned long long g_q[NSEG];    // sum(p-t) * 2^14, two's complement
__device__ unsigned long long g_cnt[NSEG];
__device__ unsigned int g_done = 0;

__device__ __forceinline__ void mbar_init(uint32_t a, uint32_t cnt) {
    asm volatile("mbarrier.init.shared.b64 [%0], %1;" :: "r"(a), "r"(cnt) : "memory");
}
__device__ __forceinline__ void mbar_arrive(uint32_t a) {
    asm volatile("mbarrier.arrive.shared.b64 _, [%0];" :: "r"(a) : "memory");
}
__device__ __forceinline__ void mbar_expect_tx(uint32_t a, uint32_t bytes) {
    asm volatile("mbarrier.arrive.expect_tx.shared.b64 _, [%0], %1;"
                 :: "r"(a), "r"(bytes) : "memory");
}
__device__ __forceinline__ void mbar_wait(uint32_t a, uint32_t parity) {
    asm volatile(
        "{\n\t.reg .pred P;\n\t"
        "WAIT_%=:\n\t"
        "mbarrier.try_wait.parity.acquire.cta.shared::cta.b64 P, [%0], %1, 0x989680;\n\t"
        "@P bra.uni DONE_%=;\n\t"
        "bra.uni WAIT_%=;\n\t"
        "DONE_%=:\n\t}"
        :: "r"(a), "r"(parity) : "memory");
}
__device__ __forceinline__ void bulk_cp(uint32_t dst, const void* src,
                                        uint32_t bytes, uint32_t mbar) {
    asm volatile(
        "cp.async.bulk.shared::cta.global.mbarrier::complete_tx::bytes "
        "[%0], [%1], %2, [%3];"
        :: "r"(dst), "l"(src), "r"(bytes), "r"(mbar) : "memory");
}

__global__ void __launch_bounds__(BLOCK, 3) ccl_kernel(
    const float* __restrict__ pred,
    const float* __restrict__ target,
    const float* __restrict__ ximg,
    float* __restrict__ out,
    int groups_per_chunk,    // 65536
    int nblocks)
{
    extern __shared__ char smem[];
    uint32_t sbase;
    asm("{ .reg .u64 t; cvta.to.shared.u64 t, %1; cvt.u32.u64 %0, t; }"
        : "=r"(sbase) : "l"(smem));

    unsigned int* hist = (unsigned int*)smem;           // [NBINS][BLOCK]
    const int tid  = threadIdx.x;
    const int lane = tid & 31;
    const int warp = tid >> 5;
    const int chunk = blockIdx.y;                       // 0..47
    const int ch    = chunk % 3;

    // this block's contiguous group range within the chunk
    const int gpb    = (groups_per_chunk + BLK_PER_CHUNK - 1) / BLK_PER_CHUNK;
    const int gstart = blockIdx.x * gpb;
    const int gcount = min(gpb, groups_per_chunk - gstart);
    const long long ebase = ((long long)chunk * groups_per_chunk + gstart) * 4;
    const int nstages = (gcount + SGROUPS - 1) / SGROUPS;

    #pragma unroll
    for (int i = 0; i < NBINS; i++) hist[i * BLOCK + tid] = 0u;
    if (tid == 0) {
        #pragma unroll
        for (int s = 0; s < NSTAGE; s++) {
            mbar_init(sbase + BAR_OFF + s * 16, 1);         // full: tx-gated
            mbar_init(sbase + BAR_OFF + s * 16 + 8, NWARP); // empty: 1 per warp
        }
    }
    __syncthreads();

    // Pre-issue the first NSTAGE stages.
    if (tid == 0) {
        for (int t = 0; t < NSTAGE && t < nstages; t++) {
            int sg  = t * SGROUPS;
            int cnt = min(SGROUPS, gcount - sg);
            uint32_t bytes = (uint32_t)cnt * 16u;
            uint32_t full  = sbase + BAR_OFF + t * 16;
            uint32_t dst   = sbase + RING_OFF + t * 3 * STAGE_BYTES;
            long long eo   = ebase + 4ll * sg;
            mbar_expect_tx(full, 3u * bytes);
            bulk_cp(dst,                   ximg   + eo, bytes, full);
            bulk_cp(dst + STAGE_BYTES,     pred   + eo, bytes, full);
            bulk_cp(dst + 2 * STAGE_BYTES, target + eo, bytes, full);
        }
    }

    unsigned int* h = &hist[tid];        // h[b*BLOCK] == hist[b][tid]

    for (int s = 0; s < nstages; s++) {
        const int slot = s % NSTAGE;
        const uint32_t full  = sbase + BAR_OFF + slot * 16;
        const uint32_t empty = full + 8;
        const uint32_t par   = (uint32_t)((s / NSTAGE) & 1);

        mbar_wait(full, par);

        int sg = s * SGROUPS;
        if (sg + tid < gcount) {
            const char* stage = smem + RING_OFF + slot * 3 * STAGE_BYTES;
            float4 xv = *(const float4*)(stage + tid * 16);
            float4 pv = *(const float4*)(stage + STAGE_BYTES + tid * 16);
            float4 tv = *(const float4*)(stage + 2 * STAGE_BYTES + tid * 16);

            float xs[4] = { xv.x, xv.y, xv.z, xv.w };
            float ds[4] = { pv.x - tv.x, pv.y - tv.y, pv.z - tv.z, pv.w - tv.w };
            #pragma unroll
            for (int j = 0; j < 4; j++) {
                int b = (int)(xs[j] * 32.0f);          // exact floor(x*32)
                if ((unsigned)b < 32u) {
                    int q = __float2int_rn(ds[j] * 16384.0f);   // d * 2^14
                    h[b * BLOCK] += 0x804000u + (unsigned)q;
                }
            }
        }
        if (lane == 0) mbar_arrive(empty);   // warp-level arrival (count=NWARP)

        // refill this slot with stage s+NSTAGE once all warps arrived
        int t = s + NSTAGE;
        if (tid == 0 && t < nstages) {
            mbar_wait(empty, par);
            int sg2  = t * SGROUPS;
            int cnt2 = min(SGROUPS, gcount - sg2);
            uint32_t bytes = (uint32_t)cnt2 * 16u;
            uint32_t dst   = sbase + RING_OFF + slot * 3 * STAGE_BYTES;
            long long eo   = ebase + 4ll * sg2;
            mbar_expect_tx(full, 3u * bytes);
            bulk_cp(dst,                   ximg   + eo, bytes, full);
            bulk_cp(dst + STAGE_BYTES,     pred   + eo, bytes, full);
            bulk_cp(dst + 2 * STAGE_BYTES, target + eo, bytes, full);
        }
    }
    __syncthreads();

    // Epilogue: warp w sweeps bins w, w+8, ...; lane reads column lane+32j
    // (conflict-free), shuffle-reduce, 2 global atomics per bin.
    for (int b = warp; b < NBINS; b += NWARP) {
        long long sumq = 0;
        long long cnt  = 0;
        #pragma unroll
        for (int j = 0; j < NWARP; j++) {
            unsigned int wd = hist[b * BLOCK + lane + 32 * j];
            unsigned int cc = wd >> 23;
            sumq += (long long)(wd & MASK23) - ((long long)cc << 14);
            cnt  += (long long)cc;
        }
        #pragma unroll
        for (int off = 16; off; off >>= 1) {
            sumq += __shfl_down_sync(0xffffffffu, sumq, off);
            cnt  += __shfl_down_sync(0xffffffffu, cnt,  off);
        }
        if (lane == 0 && cnt) {
            atomicAdd(&g_q[ch * NBINS + b], (unsigned long long)sumq);
            atomicAdd(&g_cnt[ch * NBINS + b], (unsigned long long)cnt);
        }
    }

    // Grid-done handshake; hist is dead -> reuse as scratch.
    __threadfence();
    __syncthreads();
    unsigned* lastflag = (unsigned*)&hist[0];
    double*   ws       = (double*)&hist[2 * BLOCK];
    if (tid == 0) {
        unsigned old = atomicAdd(&g_done, 1u);
        lastflag[0] = (old == (unsigned)(nblocks - 1)) ? 1u : 0u;
    }
    __syncthreads();
    if (lastflag[0]) {
        double v = 0.0;
        if (tid < NSEG) {
            unsigned long long cc = atomicExch(&g_cnt[tid], 0ull);  // read + reset
            long long qq = (long long)atomicExch(&g_q[tid], 0ull);
            if (cc) v = fabs((double)qq / ((double)cc * 16384.0));
        }
        #pragma unroll
        for (int off = 16; off; off >>= 1)
            v += __shfl_down_sync(0xffffffffu, v, off);
        if (lane == 0) ws[warp] = v;
        __syncthreads();
        if (tid == 0) {
            double tot = 0.0;
            #pragma unroll
            for (int w = 0; w < NWARP; w++) tot += ws[w];
            out[0] = (float)(tot / 96.0);
            atomicExch(&g_done, 0u);   // self-clean for next replay
        }
    }
}

extern "C" void kernel_launch(void* const* d_in, const int* in_sizes, int n_in,
                              void* d_out, int out_size) {
    const float* pred   = (const float*)d_in[0];
    const float* target = (const float*)d_in[1];
    const float* ximg   = (const float*)d_in[2];
    int n = in_sizes[0];                      // 16*3*512*512 = 12,582,912

    int groups_per_chunk = (n / 48) >> 2;     // 65536
    int nchunks = (n >> 2) / groups_per_chunk; // 48

    static int attr_set = 0;
    if (!attr_set) {
        cudaFuncSetAttribute(ccl_kernel,
                             cudaFuncAttributeMaxDynamicSharedMemorySize,
                             SMEM_TOTAL);
        attr_set = 1;
    }

    dim3 grid(BLK_PER_CHUNK, nchunks);        // 9 x 48 = 432 blocks
    ccl_kernel<<<grid, BLOCK, SMEM_TOTAL>>>(pred, target, ximg, (float*)d_out,
                                            groups_per_chunk,
                                            BLK_PER_CHUNK * nchunks);
}

// round 14
// speedup vs baseline: 1.0213x; 1.0213x over previous
#include <cuda_runtime.h>
#include <cstdint>

// ColorCurveLearningLoss: warp-specialized cp.async.bulk pipeline + per-thread
// transposed smem histogram.
// mean_p - mean_t = sum(p-t)/cnt per (channel,bin) -> one packed 32-bit token
// per element: tok = 0x804000 + round(d*2^14)  (count bits [23,32), value [0,23))
// Overflow: <=43 stages * 4 = 172 elem/thread; value <= 172*2^15 = 5.64M < 2^23;
// count <= 172 < 512.
// Block = 288 threads: warps 0-7 consume (256 threads, 1 float4-group each per
// stage), warp 8 lane 0 is a dedicated PRODUCER that keeps a 6-deep ring of
// 3x4KB stages filled via cp.async.bulk + mbarrier complete_tx. Producer only
// waits on ring-slot empty (8 consumer-warp arrivals), never on stage
// processing -> TMA queue never drains. 144KB/SM guaranteed in flight.
// Grid: 6 x 48 chunks = 288 blocks @ 2 CTA/SM = one wave.
// Globals self-clean via atomicExch in last block.

#define NBINS 32
#define NSEG 96
#define NCONS 256                        // consumer threads
#define BLOCK 288                        // + 1 producer warp
#define NWARPS_TOT 9
#define NCWARP 8                         // consumer warps
#define BLK_PER_CHUNK 6
#define NSTAGE 6
#define SGROUPS 256                      // float4 groups per stage (= NCONS)
#define STAGE_BYTES (SGROUPS * 16)       // 4096 per stream
#define MASK23 ((1u << 23) - 1u)

// dynamic smem layout
#define HIST_BYTES (NBINS * NCONS * 4)           // 32768
#define RING_OFF   HIST_BYTES
#define RING_BYTES (NSTAGE * 3 * STAGE_BYTES)    // 73728
#define BAR_OFF    (RING_OFF + RING_BYTES)
#define SMEM_TOTAL (BAR_OFF + NSTAGE * 16)       // full/empty pairs

__device__ unsigned long long g_q[NSEG];    // sum(p-t) * 2^14, two's complement
__device__ unsigned long long g_cnt[NSEG];
__device__ unsigned int g_done = 0;

__device__ __forceinline__ void mbar_init(uint32_t a, uint32_t cnt) {
    asm volatile("mbarrier.init.shared.b64 [%0], %1;" :: "r"(a), "r"(cnt) : "memory");
}
__device__ __forceinline__ void mbar_arrive(uint32_t a) {
    asm volatile("mbarrier.arrive.shared.b64 _, [%0];" :: "r"(a) : "memory");
}
__device__ __forceinline__ void mbar_expect_tx(uint32_t a, uint32_t bytes) {
    asm volatile("mbarrier.arrive.expect_tx.shared.b64 _, [%0], %1;"
                 :: "r"(a), "r"(bytes) : "memory");
}
__device__ __forceinline__ void mbar_wait(uint32_t a, uint32_t parity) {
    asm volatile(
        "{\n\t.reg .pred P;\n\t"
        "WAIT_%=:\n\t"
        "mbarrier.try_wait.parity.acquire.cta.shared::cta.b64 P, [%0], %1, 0x989680;\n\t"
        "@P bra.uni DONE_%=;\n\t"
        "bra.uni WAIT_%=;\n\t"
        "DONE_%=:\n\t}"
        :: "r"(a), "r"(parity) : "memory");
}
__device__ __forceinline__ void bulk_cp(uint32_t dst, const void* src,
                                        uint32_t bytes, uint32_t mbar) {
    asm volatile(
        "cp.async.bulk.shared::cta.global.mbarrier::complete_tx::bytes "
        "[%0], [%1], %2, [%3];"
        :: "r"(dst), "l"(src), "r"(bytes), "r"(mbar) : "memory");
}

__global__ void __launch_bounds__(BLOCK, 2) ccl_kernel(
    const float* __restrict__ pred,
    const float* __restrict__ target,
    const float* __restrict__ ximg,
    float* __restrict__ out,
    int groups_per_chunk,    // 65536
    int nblocks)
{
    extern __shared__ char smem[];
    uint32_t sbase;
    asm("{ .reg .u64 t; cvta.to.shared.u64 t, %1; cvt.u32.u64 %0, t; }"
        : "=r"(sbase) : "l"(smem));

    unsigned int* hist = (unsigned int*)smem;           // [NBINS][NCONS]
    const int tid  = threadIdx.x;
    const int lane = tid & 31;
    const int warp = tid >> 5;
    const int chunk = blockIdx.y;                       // 0..47
    const int ch    = chunk % 3;

    // this block's contiguous group range within the chunk
    const int gpb    = (groups_per_chunk + BLK_PER_CHUNK - 1) / BLK_PER_CHUNK;
    const int gstart = blockIdx.x * gpb;
    const int gcount = min(gpb, groups_per_chunk - gstart);
    const long long ebase = ((long long)chunk * groups_per_chunk + gstart) * 4;
    const int nstages = (gcount + SGROUPS - 1) / SGROUPS;

    if (tid < NCONS) {
        #pragma unroll
        for (int i = 0; i < NBINS; i++) hist[i * NCONS + tid] = 0u;
    }
    if (tid == 0) {
        #pragma unroll
        for (int s = 0; s < NSTAGE; s++) {
            mbar_init(sbase + BAR_OFF + s * 16, 1);          // full: tx-gated
            mbar_init(sbase + BAR_OFF + s * 16 + 8, NCWARP); // empty: 1 per cons warp
        }
    }
    __syncthreads();

    if (warp < NCWARP) {
        // ---------------- consumers ----------------
        unsigned int* h = &hist[tid];    // h[b*NCONS] == hist[b][tid]
        for (int s = 0; s < nstages; s++) {
            const int slot = s % NSTAGE;
            const uint32_t full  = sbase + BAR_OFF + slot * 16;
            const uint32_t empty = full + 8;
            mbar_wait(full, (uint32_t)((s / NSTAGE) & 1));

            int sg = s * SGROUPS;
            if (sg + tid < gcount) {
                const char* stage = smem + RING_OFF + slot * 3 * STAGE_BYTES;
                float4 xv = *(const float4*)(stage + tid * 16);
                float4 pv = *(const float4*)(stage + STAGE_BYTES + tid * 16);
                float4 tv = *(const float4*)(stage + 2 * STAGE_BYTES + tid * 16);

                float xs[4] = { xv.x, xv.y, xv.z, xv.w };
                float ds[4] = { pv.x - tv.x, pv.y - tv.y, pv.z - tv.z, pv.w - tv.w };
                #pragma unroll
                for (int j = 0; j < 4; j++) {
                    int b = (int)(xs[j] * 32.0f);      // exact floor(x*32)
                    if ((unsigned)b < 32u) {
                        int q = __float2int_rn(ds[j] * 16384.0f);   // d * 2^14
                        h[b * NCONS] += 0x804000u + (unsigned)q;
                    }
                }
            }
            if (lane == 0) mbar_arrive(empty);
        }
    } else if (lane == 0) {
        // ---------------- producer (warp 8, lane 0) ----------------
        for (int t = 0; t < nstages; t++) {
            const int slot = t % NSTAGE;
            const uint32_t full  = sbase + BAR_OFF + slot * 16;
            const uint32_t empty = full + 8;
            if (t >= NSTAGE)
                mbar_wait(empty, (uint32_t)(((t / NSTAGE) - 1) & 1));

            int sg  = t * SGROUPS;
            int cnt = min(SGROUPS, gcount - sg);
            uint32_t bytes = (uint32_t)cnt * 16u;
            uint32_t dst   = sbase + RING_OFF + slot * 3 * STAGE_BYTES;
            long long eo   = ebase + 4ll * sg;
            mbar_expect_tx(full, 3u * bytes);
            bulk_cp(dst,                   ximg   + eo, bytes, full);
            bulk_cp(dst + STAGE_BYTES,     pred   + eo, bytes, full);
            bulk_cp(dst + 2 * STAGE_BYTES, target + eo, bytes, full);
        }
    }
    __syncthreads();

    // Epilogue: 9 warps sweep bins; lane reads columns lane+32j (conflict-free),
    // shuffle-reduce, 2 global atomics per bin.
    for (int b = warp; b < NBINS; b += NWARPS_TOT) {
        long long sumq = 0;
        long long cnt  = 0;
        #pragma unroll
        for (int j = 0; j < NCONS / 32; j++) {
            unsigned int wd = hist[b * NCONS + lane + 32 * j];
            unsigned int cc = wd >> 23;
            sumq += (long long)(wd & MASK23) - ((long long)cc << 14);
            cnt  += (long long)cc;
        }
        #pragma unroll
        for (int off = 16; off; off >>= 1) {
            sumq += __shfl_down_sync(0xffffffffu, sumq, off);
            cnt  += __shfl_down_sync(0xffffffffu, cnt,  off);
        }
        if (lane == 0 && cnt) {
            atomicAdd(&g_q[ch * NBINS + b], (unsigned long long)sumq);
            atomicAdd(&g_cnt[ch * NBINS + b], (unsigned long long)cnt);
        }
    }

    // Grid-done handshake; hist is dead -> reuse as scratch.
    __threadfence();
    __syncthreads();
    unsigned* lastflag = (unsigned*)&hist[0];
    double*   ws       = (double*)&hist[2 * NCONS];
    if (tid == 0) {
        unsigned old = atomicAdd(&g_done, 1u);
        lastflag[0] = (old == (unsigned)(nblocks - 1)) ? 1u : 0u;
    }
    __syncthreads();
    if (lastflag[0]) {
        double v = 0.0;
        if (tid < NSEG) {
            unsigned long long cc = atomicExch(&g_cnt[tid], 0ull);  // read + reset
            long long qq = (long long)atomicExch(&g_q[tid], 0ull);
            if (cc) v = fabs((double)qq / ((double)cc * 16384.0));
        }
        #pragma unroll
        for (int off = 16; off; off >>= 1)
            v += __shfl_down_sync(0xffffffffu, v, off);
        if (lane == 0) ws[warp] = v;
        __syncthreads();
        if (tid == 0) {
            double tot = 0.0;
            #pragma unroll
            for (int w = 0; w < NWARPS_TOT; w++) tot += ws[w];
            out[0] = (float)(tot / 96.0);
            atomicExch(&g_done, 0u);   // self-clean for next replay
        }
    }
}

extern "C" void kernel_launch(void* const* d_in, const int* in_sizes, int n_in,
                              void* d_out, int out_size) {
    const float* pred   = (const float*)d_in[0];
    const float* target = (const float*)d_in[1];
    const float* ximg   = (const float*)d_in[2];
    int n = in_sizes[0];                      // 16*3*512*512 = 12,582,912

    int groups_per_chunk = (n / 48) >> 2;     // 65536
    int nchunks = (n >> 2) / groups_per_chunk; // 48

    static int attr_set = 0;
    if (!attr_set) {
        cudaFuncSetAttribute(ccl_kernel,
                             cudaFuncAttributeMaxDynamicSharedMemorySize,
                             SMEM_TOTAL);
        attr_set = 1;
    }

    dim3 grid(BLK_PER_CHUNK, nchunks);        // 6 x 48 = 288 blocks
    ccl_kernel<<<grid, BLOCK, SMEM_TOTAL>>>(pred, target, ximg, (float*)d_out,
                                            groups_per_chunk,
                                            BLK_PER_CHUNK * nchunks);
}